// round 7
// baseline (speedup 1.0000x reference)
#include <cuda_runtime.h>

#define BB 64      // batch
#define SS 512     // sequence length
#define EE 256     // embedding dim
#define HH 512     // hidden
#define GG 2048    // 4*H gate rows

typedef unsigned long long u64;
typedef unsigned int u32;

// ---------------------------------------------------------------------------
// Device globals
// ---------------------------------------------------------------------------
__device__ u32 g_wf[128][32];                 // per-CTA h write-flags, 128B padded
__device__ float g_xg[SS * GG * BB];          // x_gates [s][g][b]
__device__ float g_h[4][HH * BB];             // h ring: slot s&3 = h(s), [k][b]

// ---------------------------------------------------------------------------
// f32x2 helpers (packed FFMA2 -- only reachable via PTX)
// ---------------------------------------------------------------------------
__device__ __forceinline__ u64 fma2(u64 a, u64 b, u64 c) {
    u64 d; asm("fma.rn.f32x2 %0, %1, %2, %3;" : "=l"(d) : "l"(a), "l"(b), "l"(c)); return d;
}
__device__ __forceinline__ u64 pack2(float x, float y) {
    u64 d; asm("mov.b64 %0, {%1, %2};" : "=l"(d) : "f"(x), "f"(y)); return d;
}
__device__ __forceinline__ float2 unpack2(u64 v) {
    float2 r; asm("mov.b64 {%0, %1}, %2;" : "=f"(r.x), "=f"(r.y) : "l"(v)); return r;
}
__device__ __forceinline__ float sigf(float x) { return 1.f / (1.f + __expf(-x)); }
__device__ __forceinline__ float tanh_f(float x) { return 2.f / (1.f + __expf(-2.f * x)) - 1.f; }

// wait until the 4 padded flags at fl[0..3] reach target (lanes 0-3 poll)
__device__ __forceinline__ void wait4(const u32* fl, u32 target, int lane) {
    int ok, first = 1;
    do {
        if (!first) __nanosleep(20);
        first = 0;
        ok = 1;
        if (lane < 4) {
            u32 f;
            asm volatile("ld.acquire.gpu.global.u32 %0, [%1];"
                         : "=r"(f) : "l"(fl + lane * 32));
            ok = ((int)(f - target) >= 0);
        }
    } while (__all_sync(0xffffffffu, ok) == 0);
}

// ---------------------------------------------------------------------------
// Phase A: x_gates[s][g][b] = emb[seq[b][s]] . W_ih[g] + b_ih[g] + b_hh[g]
// (unchanged: 128x64 tile, BK=16, 8Mx4N f32x2 micro, conflict-free)
// ---------------------------------------------------------------------------
__global__ void __launch_bounds__(256) xgates_gemm(
    const void* __restrict__ seq,
    const float* __restrict__ emb,
    const float* __restrict__ Wih,
    const float* __restrict__ bih,
    const float* __restrict__ bhh)
{
    __shared__ float  As[16][132];
    __shared__ float2 Bs2[16][66];
    __shared__ int rows[128];
    __shared__ int s_is64;

    const int tid = threadIdx.x;
    const int s0 = blockIdx.y * 2;
    const int g0 = blockIdx.x * 64;

    if (tid == 0) s_is64 = 1;
    __syncthreads();
    if (tid < 64) {
        if (((const u32*)seq)[2 * tid + 1] != 0u) s_is64 = 0;
    }
    __syncthreads();
    if (tid < 128) {
        int b = tid & 63, sl = tid >> 6;
        int idx;
        if (s_is64) idx = (int)((const long long*)seq)[b * SS + s0 + sl];
        else        idx = ((const int*)seq)[b * SS + s0 + sl];
        rows[tid] = idx;
    }
    __syncthreads();

    const int tx = tid & 15;
    const int ty = tid >> 4;
    const int arow = tid >> 1;
    const int ak   = (tid & 1) * 8;
    const int wrow = tid >> 2;
    const int wk   = (tid & 3) * 4;

    u64 cc[4][4];
    #pragma unroll
    for (int p = 0; p < 4; p++)
        #pragma unroll
        for (int jn = 0; jn < 4; jn++) cc[p][jn] = 0ull;

    for (int k0 = 0; k0 < EE; k0 += 16) {
        const float* ap = emb + (size_t)rows[arow] * EE + k0 + ak;
        float4 a0 = *(const float4*)ap;
        float4 a1 = *(const float4*)(ap + 4);
        As[ak + 0][arow] = a0.x; As[ak + 1][arow] = a0.y;
        As[ak + 2][arow] = a0.z; As[ak + 3][arow] = a0.w;
        As[ak + 4][arow] = a1.x; As[ak + 5][arow] = a1.y;
        As[ak + 6][arow] = a1.z; As[ak + 7][arow] = a1.w;
        float4 wv = *(const float4*)&Wih[(size_t)(g0 + wrow) * EE + k0 + wk];
        Bs2[wk + 0][wrow] = make_float2(wv.x, wv.x);
        Bs2[wk + 1][wrow] = make_float2(wv.y, wv.y);
        Bs2[wk + 2][wrow] = make_float2(wv.z, wv.z);
        Bs2[wk + 3][wrow] = make_float2(wv.w, wv.w);
        __syncthreads();

        #pragma unroll
        for (int kk = 0; kk < 16; kk++) {
            u64 a0p = *(const u64*)&As[kk][0 * 32 + tx * 2];
            u64 a1p = *(const u64*)&As[kk][1 * 32 + tx * 2];
            u64 a2p = *(const u64*)&As[kk][2 * 32 + tx * 2];
            u64 a3p = *(const u64*)&As[kk][3 * 32 + tx * 2];
            u64 w0 = *(const u64*)&Bs2[kk][ty * 4 + 0];
            u64 w1 = *(const u64*)&Bs2[kk][ty * 4 + 1];
            u64 w2 = *(const u64*)&Bs2[kk][ty * 4 + 2];
            u64 w3 = *(const u64*)&Bs2[kk][ty * 4 + 3];
            cc[0][0] = fma2(a0p, w0, cc[0][0]); cc[1][0] = fma2(a1p, w0, cc[1][0]);
            cc[2][0] = fma2(a2p, w0, cc[2][0]); cc[3][0] = fma2(a3p, w0, cc[3][0]);
            cc[0][1] = fma2(a0p, w1, cc[0][1]); cc[1][1] = fma2(a1p, w1, cc[1][1]);
            cc[2][1] = fma2(a2p, w1, cc[2][1]); cc[3][1] = fma2(a3p, w1, cc[3][1]);
            cc[0][2] = fma2(a0p, w2, cc[0][2]); cc[1][2] = fma2(a1p, w2, cc[1][2]);
            cc[2][2] = fma2(a2p, w2, cc[2][2]); cc[3][2] = fma2(a3p, w2, cc[3][2]);
            cc[0][3] = fma2(a0p, w3, cc[0][3]); cc[1][3] = fma2(a1p, w3, cc[1][3]);
            cc[2][3] = fma2(a2p, w3, cc[2][3]); cc[3][3] = fma2(a3p, w3, cc[3][3]);
        }
        __syncthreads();
    }

    #pragma unroll
    for (int jn = 0; jn < 4; jn++) {
        int g = g0 + ty * 4 + jn;
        float bsum = bih[g] + bhh[g];
        #pragma unroll
        for (int p = 0; p < 4; p++) {
            float2 v = unpack2(cc[p][jn]);
            int s = s0 + (p >> 1);
            int b = (p & 1) * 32 + tx * 2;
            *(float2*)&g_xg[(size_t)s * (GG * BB) + (size_t)g * BB + b] =
                make_float2(v.x + bsum, v.y + bsum);
        }
    }
}

// ---------------------------------------------------------------------------
// Phase B: persistent LSTM recurrence, fine-grained dataflow sync.
// 128 CTAs x 256 threads (8 warps). CTA owns 4 h-columns (8 f32x2 streams).
// Warp wi owns k-range [wi*64, +64) x all 64 b. Each 16-k chunk c is
// produced by exactly 4 CTAs (wi*16+c*4 .. +4): wait per-chunk, padded
// flags (one 128B line each), interleaved with double-buffered prefetch.
// Ring depth 4: all 8 warps jointly cover all 128 flags each step before
// the CTA's own store+bump -> slot reuse safe; monotonic -> replay safe.
// ---------------------------------------------------------------------------
__global__ void __launch_bounds__(256, 1) lstm_kernel(
    const float* __restrict__ Whh, float* __restrict__ out, int write_c)
{
    extern __shared__ float smf[];
    float*  Ws  = smf;                      // (st*512+k)*2 : {w_jA, w_jB}
    float2* scp = (float2*)(smf + 8192);    // [st8][bh2][kr8][lane32]
    __shared__ u32 s_base;

    const int tid  = threadIdx.x;
    const int wi   = tid >> 5;
    const int lane = tid & 31;
    const int cta  = blockIdx.x;
    const int j0   = cta * 4;
    const int kbase = wi * 64;

    if (tid == 0) s_base = g_wf[cta][0];

    #pragma unroll
    for (int st = 0; st < 8; st++) {
        int g = st >> 1, jp = st & 1;
        const float* r0 = Whh + (size_t)(g * HH + j0 + 2 * jp) * HH;
        const float* r1 = r0 + HH;
        #pragma unroll
        for (int i = 0; i < 2; i++) {
            int k = tid + i * 256;
            *(float2*)&Ws[(st * 512 + k) * 2] = make_float2(r0[k], r1[k]);
        }
    }
    __syncthreads();

    const int b  = tid & 63;
    const int jj = tid >> 6;
    const int j  = j0 + jj;
    const int jp_r  = jj >> 1;
    const int comp  = jj & 1;
    const int bh_r  = b >> 5;
    const int lane_r = b & 31;
    const u32 base = s_base;

    float c_reg = 0.f, h_val = 0.f;

    #pragma unroll 1
    for (int s = 0; s < SS; s++) {
        float xgv[4];
        const float* xgs = g_xg + (size_t)s * (GG * BB);
        #pragma unroll
        for (int g = 0; g < 4; g++)
            xgv[g] = __ldg(&xgs[(g * HH + j) * BB + b]);

        u64 acc[8][2];
        #pragma unroll
        for (int st = 0; st < 8; st++) { acc[st][0] = 0ull; acc[st][1] = 0ull; }

        if (s > 0) {
            const u32 target = base + (u32)s;
            const float* hsrc = g_h[(s - 1) & 3];
            float hreg[2][32];

            // wait for the 4 producers of chunk 0, then prefetch it
            wait4(&g_wf[wi * 16][0], target, lane);
            #pragma unroll
            for (int i = 0; i < 16; i++) {
                hreg[0][i]      = __ldcg(&hsrc[(kbase + i) * 64 + lane]);
                hreg[0][16 + i] = __ldcg(&hsrc[(kbase + i) * 64 + 32 + lane]);
            }

            #pragma unroll
            for (int c = 0; c < 4; c++) {
                const int cur = c & 1, nxt = cur ^ 1;
                if (c < 3) {
                    // wait for producers of chunk c+1, prefetch into other buffer
                    wait4(&g_wf[wi * 16 + (c + 1) * 4][0], target, lane);
                    const int kn = kbase + (c + 1) * 16;
                    #pragma unroll
                    for (int i = 0; i < 16; i++) {
                        hreg[nxt][i]      = __ldcg(&hsrc[(kn + i) * 64 + lane]);
                        hreg[nxt][16 + i] = __ldcg(&hsrc[(kn + i) * 64 + 32 + lane]);
                    }
                }
                const int kg0 = kbase + c * 16;
                #pragma unroll
                for (int kk = 0; kk < 16; kk += 2) {
                    const int kg = kg0 + kk;
                    u64 dA0 = pack2(hreg[cur][kk],          hreg[cur][kk]);
                    u64 dB0 = pack2(hreg[cur][16 + kk],     hreg[cur][16 + kk]);
                    u64 dA1 = pack2(hreg[cur][kk + 1],      hreg[cur][kk + 1]);
                    u64 dB1 = pack2(hreg[cur][16 + kk + 1], hreg[cur][16 + kk + 1]);
                    #pragma unroll
                    for (int st = 0; st < 8; st++) {
                        ulonglong2 wv = *(const ulonglong2*)&Ws[(st * 512 + kg) * 2];
                        acc[st][0] = fma2(dA0, wv.x, acc[st][0]);
                        acc[st][1] = fma2(dB0, wv.x, acc[st][1]);
                        acc[st][0] = fma2(dA1, wv.y, acc[st][0]);
                        acc[st][1] = fma2(dB1, wv.y, acc[st][1]);
                    }
                }
            }
        }

        // partials -> scratch [st][bh][kr][lane]
        #pragma unroll
        for (int st = 0; st < 8; st++) {
            scp[((st * 2 + 0) * 8 + wi) * 32 + lane] = *(float2*)&acc[st][0];
            scp[((st * 2 + 1) * 8 + wi) * 32 + lane] = *(float2*)&acc[st][1];
        }
        __syncthreads();

        float gt[4];
        #pragma unroll
        for (int g = 0; g < 4; g++) {
            int st = g * 2 + jp_r;
            const float2* rb = &scp[((st * 2 + bh_r) * 8) * 32 + lane_r];
            float sx = 0.f, sy = 0.f;
            #pragma unroll
            for (int kr = 0; kr < 8; kr++) { float2 p = rb[kr * 32]; sx += p.x; sy += p.y; }
            gt[g] = (comp ? sy : sx) + xgv[g];
        }
        float ig = sigf(gt[0]), fg = sigf(gt[1]);
        float gg = tanh_f(gt[2]), og = sigf(gt[3]);
        c_reg = fg * c_reg + ig * gg;
        h_val = og * tanh_f(c_reg);

        __stcg(&g_h[s & 3][j * 64 + b], h_val);
        __syncthreads();
        if (tid == 0) {
            asm volatile("red.release.gpu.global.add.u32 [%0], %1;"
                         :: "l"(&g_wf[cta][0]), "r"(1u) : "memory");
        }
    }

    out[b * HH + j] = h_val;
    if (write_c) out[BB * HH + b * HH + j] = c_reg;
}

// ---------------------------------------------------------------------------
// kernel_launch
// ---------------------------------------------------------------------------
extern "C" void kernel_launch(void* const* d_in, const int* in_sizes, int n_in,
                              void* d_out, int out_size)
{
    const void*  seq = d_in[0];
    const float* emb = (const float*)d_in[1];
    const float* Wih = (const float*)d_in[2];
    const float* Whh = (const float*)d_in[3];
    const float* bih = (const float*)d_in[4];
    const float* bhh = (const float*)d_in[5];
    float* out = (float*)d_out;

    (void)in_sizes; (void)n_in;
    int write_c = (out_size >= 2 * BB * HH) ? 1 : 0;

    static const int kSmem = (8192 + 8192) * (int)sizeof(float);
    cudaFuncSetAttribute(lstm_kernel, cudaFuncAttributeMaxDynamicSharedMemorySize, kSmem);

    xgates_gemm<<<dim3(GG / 64, SS / 2), 256>>>(seq, emb, Wih, bih, bhh);
    lstm_kernel<<<HH / 4, 256, kSmem>>>(Whh, out, write_c);
}